// round 2
// baseline (speedup 1.0000x reference)
#include <cuda_runtime.h>
#include <stdint.h>

// Problem shapes (fixed by the dataset).
#define BB 64
#define PP 2048
#define GG 512
#define GH 256          // gt half size (gsplit = 2)

// Scratch. Packed per (half, image, pred): (iou_bits<<32) | (511 - g_global).
__device__ unsigned long long g_pack[2 * BB * PP];
__device__ float g_ap[BB];

// ---------------------------------------------------------------------------
// K1: per (image, pred, gt-half) compute first-max argmax_g IoU and max value.
// 256 threads, 2 preds/thread, 256 gts in smem. grid = (PP/512, BB, 2).
// ---------------------------------------------------------------------------
__global__ __launch_bounds__(256) void k_bestiou(
    const float* __restrict__ pred_boxes,   // [B,P,4] xywh
    const float* __restrict__ gt_boxes)     // [B,G,4] xywh
{
    const int b  = blockIdx.y;
    const int zh = blockIdx.z;                    // gt half
    const int p0 = blockIdx.x * 512 + threadIdx.x;
    const int p1 = p0 + 256;

    __shared__ float4 sbox[GH];   // x1,y1,x2,y2
    __shared__ float  sarea[GH];

    const float4* gbp = reinterpret_cast<const float4*>(
        gt_boxes + ((size_t)b * GG + (size_t)zh * GH) * 4);
    if (threadIdx.x < GH) {
        float4 v = gbp[threadIdx.x];
        float x2 = v.x + v.z;
        float y2 = v.y + v.w;
        sbox[threadIdx.x]  = make_float4(v.x, v.y, x2, y2);
        sarea[threadIdx.x] = fabsf((x2 - v.x) * (y2 - v.y));
    }
    __syncthreads();

    const float4* pbp = reinterpret_cast<const float4*>(pred_boxes + (size_t)b * PP * 4);
    float4 a = pbp[p0];
    float4 c = pbp[p1];
    const float ax1 = a.x, ay1 = a.y, ax2 = a.x + a.z, ay2 = a.y + a.w;
    const float cx1 = c.x, cy1 = c.y, cx2 = c.x + c.z, cy2 = c.y + c.w;
    const float aa = fabsf((ax2 - ax1) * (ay2 - ay1)) + 1e-9f;  // pa + eps hoisted
    const float ca = fabsf((cx2 - cx1) * (cy2 - cy1)) + 1e-9f;

    float best0 = -1.0f, best1 = -1.0f;
    int   bg0 = 0, bg1 = 0;

#pragma unroll 4
    for (int g = 0; g < GH; ++g) {
        float4 gb = sbox[g];
        float sa  = sarea[g];
        // pred 0
        {
            float ix1 = fmaxf(ax1, gb.x);
            float iy1 = fmaxf(ay1, gb.y);
            float ix2 = fminf(ax2, gb.z);
            float iy2 = fminf(ay2, gb.w);
            float iw  = fmaxf(ix2 - ix1, 0.0f);
            float ih  = fmaxf(iy2 - iy1, 0.0f);
            float inter = iw * ih;
            float u   = (aa + sa) - inter;
            float iou = __fdividef(inter, u);
            if (iou > best0) { best0 = iou; bg0 = g; }   // strict > keeps FIRST max
        }
        // pred 1
        {
            float ix1 = fmaxf(cx1, gb.x);
            float iy1 = fmaxf(cy1, gb.y);
            float ix2 = fminf(cx2, gb.z);
            float iy2 = fminf(cy2, gb.w);
            float iw  = fmaxf(ix2 - ix1, 0.0f);
            float ih  = fmaxf(iy2 - iy1, 0.0f);
            float inter = iw * ih;
            float u   = (ca + sa) - inter;
            float iou = __fdividef(inter, u);
            if (iou > best1) { best1 = iou; bg1 = g; }
        }
    }

    const int goff = zh * GH;
    unsigned long long* outp = g_pack + (size_t)zh * BB * PP + (size_t)b * PP;
    outp[p0] = ((unsigned long long)__float_as_uint(best0) << 32)
             | (unsigned int)(511 - (bg0 + goff));
    outp[p1] = ((unsigned long long)__float_as_uint(best1) << 32)
             | (unsigned int)(511 - (bg1 + goff));
}

// ---------------------------------------------------------------------------
// K2: per image — stable descending sort of scores (bitonic, 1024 threads),
// merge gt-halves, greedy TP via min-rank-per-gt, prefix sum, AP.
// ---------------------------------------------------------------------------
__global__ __launch_bounds__(1024) void k_ap(
    const float* __restrict__ pred_scores,   // [B,P]
    const int*   __restrict__ pred_classes,  // [B,P]
    const int*   __restrict__ gt_classes)    // [B,G]
{
    const int b   = blockIdx.x;
    const int tid = threadIdx.x;

    __shared__ unsigned long long skey[PP];   // (score_bits<<32) | (~idx)
    __shared__ unsigned short     sgc[PP];    // bit15 = cand, low bits = g
    __shared__ int                smin[GG];   // min tp-candidate rank per gt
    __shared__ int                wsum[32];
    __shared__ float              wred[32];

    // Keys: scores >= 0 so raw float bits are order-monotonic.
    // (~idx) low bits => equal scores keep smaller idx first (stable argsort).
    skey[tid]        = ((unsigned long long)__float_as_uint(pred_scores[b * PP + tid]) << 32)
                     | (unsigned int)(0xFFFFFFFFu - tid);
    skey[tid + 1024] = ((unsigned long long)__float_as_uint(pred_scores[b * PP + tid + 1024]) << 32)
                     | (unsigned int)(0xFFFFFFFFu - (tid + 1024));
    if (tid < GG) smin[tid] = 0x7FFFFFFF;
    __syncthreads();

    // Bitonic sort, descending: exactly one compare-exchange per thread/pass.
    for (int k = 2; k <= PP; k <<= 1) {
        for (int j = k >> 1; j > 0; j >>= 1) {
            int i   = ((tid & ~(j - 1)) << 1) | (tid & (j - 1));
            int ixj = i | j;
            bool desc = ((i & k) == 0);
            unsigned long long x = skey[i];
            unsigned long long y = skey[ixj];
            bool sw = desc ? (x < y) : (x > y);
            if (sw) { skey[i] = y; skey[ixj] = x; }
            __syncthreads();
        }
    }

    // Candidates + min rank per gt (merge the two gt-half results).
    const unsigned long long* pk0 = g_pack + (size_t)b * PP;
    const unsigned long long* pk1 = g_pack + (size_t)BB * PP + (size_t)b * PP;
#pragma unroll
    for (int rr = 0; rr < 2; ++rr) {
        int r = tid + rr * 1024;
        int p = (int)(0xFFFFFFFFu - (unsigned int)(skey[r] & 0xFFFFFFFFu));
        unsigned long long v0 = pk0[p];
        unsigned long long v1 = pk1[p];
        unsigned long long v  = (v1 > v0) ? v1 : v0;   // iou desc, tie -> lower g
        int   g    = 511 - (int)(v & 0x3FF);
        float biou = __uint_as_float((unsigned int)(v >> 32));
        bool cand = (biou > 0.5f) && (pred_classes[b * PP + p] == gt_classes[b * GG + g]);
        sgc[r] = (unsigned short)(g | (cand ? 0x8000 : 0));
        if (cand) atomicMin(&smin[g], r);
    }
    __syncthreads();

    // tp[rank] = cand && (rank is the first candidate rank for its gt).
    const int base = tid * 2;
    int t0, t1;
    {
        unsigned short v;
        v = sgc[base + 0]; t0 = ((v & 0x8000) && smin[v & 0x7FFF] == base + 0) ? 1 : 0;
        v = sgc[base + 1]; t1 = ((v & 0x8000) && smin[v & 0x7FFF] == base + 1) ? 1 : 0;
    }
    int lsum = t0 + t1;

    // Block inclusive scan of per-thread sums (32 warps).
    const int lane = tid & 31, wid = tid >> 5;
    int sc = lsum;
    for (int o = 1; o < 32; o <<= 1) {
        int v = __shfl_up_sync(0xFFFFFFFFu, sc, o);
        if (lane >= o) sc += v;
    }
    if (lane == 31) wsum[wid] = sc;
    __syncthreads();
    if (wid == 0) {
        int v = wsum[lane];
        for (int o = 1; o < 32; o <<= 1) {
            int u = __shfl_up_sync(0xFFFFFFFFu, v, o);
            if (lane >= o) v += u;
        }
        wsum[lane] = v;
    }
    __syncthreads();
    int j = (sc - lsum) + (wid > 0 ? wsum[wid - 1] : 0);   // exclusive tp count

    // AP terms: at tp rank k (1-indexed) with cum j:
    //   0.5 * ( j/k + (k==1 ? 1 : (j-1)/(k-1)) ); recall step 1/G folded at end.
    float term = 0.0f;
    int ks = base + 1;
    if (t0) { ++j; term += 0.5f * ((float)j / (float)ks + ((ks == 1) ? 1.0f : (float)(j - 1) / (float)(ks - 1))); }
    ++ks;
    if (t1) { ++j; term += 0.5f * ((float)j / (float)ks + (float)(j - 1) / (float)(ks - 1)); }

    // Block reduce term sum.
    float ts = term;
    for (int o = 16; o > 0; o >>= 1) ts += __shfl_down_sync(0xFFFFFFFFu, ts, o);
    if (lane == 0) wred[wid] = ts;
    __syncthreads();
    if (wid == 0) {
        float v = wred[lane];
        for (int o = 16; o > 0; o >>= 1) v += __shfl_down_sync(0xFFFFFFFFu, v, o);
        if (lane == 0) g_ap[b] = v / (float)GG;
    }
}

// ---------------------------------------------------------------------------
// K3: deterministic mean of 64 per-image APs (fixed shuffle tree).
// ---------------------------------------------------------------------------
__global__ void k_mean(float* __restrict__ out)
{
    int lane = threadIdx.x;   // one warp
    float v = g_ap[lane] + g_ap[lane + 32];
    for (int o = 16; o > 0; o >>= 1) v += __shfl_down_sync(0xFFFFFFFFu, v, o);
    if (lane == 0) out[0] = v * (1.0f / (float)BB);
}

// ---------------------------------------------------------------------------
extern "C" void kernel_launch(void* const* d_in, const int* in_sizes, int n_in,
                              void* d_out, int out_size)
{
    const float* pred_boxes   = (const float*)d_in[0];
    const float* pred_scores  = (const float*)d_in[1];
    const int*   pred_classes = (const int*)d_in[2];
    const float* gt_boxes     = (const float*)d_in[3];
    const int*   gt_classes   = (const int*)d_in[4];
    float* out = (float*)d_out;

    dim3 g1(PP / 512, BB, 2);
    k_bestiou<<<g1, 256>>>(pred_boxes, gt_boxes);
    k_ap<<<BB, 1024>>>(pred_scores, pred_classes, gt_classes);
    k_mean<<<1, 32>>>(out);
}

// round 5
// speedup vs baseline: 1.2193x; 1.2193x over previous
#include <cuda_runtime.h>
#include <stdint.h>

// Problem shapes (fixed by the dataset).
#define BB 64
#define PP 2048
#define GG 512
#define NZ 4
#define GH (GG / NZ)    // 128 gts per tile

// Scratch. Packed per (quarter, image, pred): (iou_bits<<32) | (511 - g_global).
__device__ unsigned long long g_pack[NZ * BB * PP];
// Dense per (image, pred): (rank<<9) | ginv, where ginv = 511 - g.
// 0xFFFFFFFF = not a candidate.
__device__ unsigned int g_cand[BB * PP];
__device__ float g_ap[BB];

// ---------------------------------------------------------------------------
// K1: per (image, pred, gt-quarter) first-max argmax_g IoU + max value.
// 256 threads, 2 preds/thread, 128 gts in smem. grid = (PP/512, BB, NZ).
// ---------------------------------------------------------------------------
__global__ __launch_bounds__(256) void k_bestiou(
    const float* __restrict__ pred_boxes,   // [B,P,4] xywh
    const float* __restrict__ gt_boxes)     // [B,G,4] xywh
{
    const int b  = blockIdx.y;
    const int zh = blockIdx.z;
    const int p0 = blockIdx.x * 512 + threadIdx.x;
    const int p1 = p0 + 256;

    __shared__ float4 sbox[GH];   // x1,y1,x2,y2
    __shared__ float  sarea[GH];

    const float4* gbp = reinterpret_cast<const float4*>(
        gt_boxes + ((size_t)b * GG + (size_t)zh * GH) * 4);
    if (threadIdx.x < GH) {
        float4 v = gbp[threadIdx.x];
        float x2 = v.x + v.z;
        float y2 = v.y + v.w;
        sbox[threadIdx.x]  = make_float4(v.x, v.y, x2, y2);
        sarea[threadIdx.x] = fabsf((x2 - v.x) * (y2 - v.y));
    }
    __syncthreads();

    const float4* pbp = reinterpret_cast<const float4*>(pred_boxes + (size_t)b * PP * 4);
    float4 a = pbp[p0];
    float4 c = pbp[p1];
    const float ax1 = a.x, ay1 = a.y, ax2 = a.x + a.z, ay2 = a.y + a.w;
    const float cx1 = c.x, cy1 = c.y, cx2 = c.x + c.z, cy2 = c.y + c.w;
    const float aa = fabsf((ax2 - ax1) * (ay2 - ay1)) + 1e-9f;  // pa + eps hoisted
    const float ca = fabsf((cx2 - cx1) * (cy2 - cy1)) + 1e-9f;

    float best0 = -1.0f, best1 = -1.0f;
    int   bg0 = 0, bg1 = 0;

#pragma unroll 4
    for (int g = 0; g < GH; ++g) {
        float4 gb = sbox[g];
        float sa  = sarea[g];
        {
            float ix1 = fmaxf(ax1, gb.x);
            float iy1 = fmaxf(ay1, gb.y);
            float ix2 = fminf(ax2, gb.z);
            float iy2 = fminf(ay2, gb.w);
            float iw  = fmaxf(ix2 - ix1, 0.0f);
            float ih  = fmaxf(iy2 - iy1, 0.0f);
            float inter = iw * ih;
            float u   = (aa + sa) - inter;
            float iou = __fdividef(inter, u);
            if (iou > best0) { best0 = iou; bg0 = g; }   // strict > keeps FIRST max
        }
        {
            float ix1 = fmaxf(cx1, gb.x);
            float iy1 = fmaxf(cy1, gb.y);
            float ix2 = fminf(cx2, gb.z);
            float iy2 = fminf(cy2, gb.w);
            float iw  = fmaxf(ix2 - ix1, 0.0f);
            float ih  = fmaxf(iy2 - iy1, 0.0f);
            float inter = iw * ih;
            float u   = (ca + sa) - inter;
            float iou = __fdividef(inter, u);
            if (iou > best1) { best1 = iou; bg1 = g; }
        }
    }

    const int goff = zh * GH;
    unsigned long long* outp = g_pack + (size_t)zh * BB * PP + (size_t)b * PP;
    outp[p0] = ((unsigned long long)__float_as_uint(best0) << 32)
             | (unsigned int)(511 - (bg0 + goff));
    outp[p1] = ((unsigned long long)__float_as_uint(best1) << 32)
             | (unsigned int)(511 - (bg1 + goff));
}

// ---------------------------------------------------------------------------
// K2a: merge quarters, detect candidates, compute exact stable-sort rank for
// candidates only (warp-cooperative count). Writes dense g_cand (det. order).
// grid = (PP/256, BB), 256 threads.
// ---------------------------------------------------------------------------
__global__ __launch_bounds__(256) void k_cand(
    const float* __restrict__ pred_scores,   // [B,P]
    const int*   __restrict__ pred_classes,  // [B,P]
    const int*   __restrict__ gt_classes)    // [B,G]
{
    const int b   = blockIdx.y;
    const int tid = threadIdx.x;
    const int p   = blockIdx.x * 256 + tid;

    __shared__ float ssc[PP];   // all scores of image b

    const float4* sp = reinterpret_cast<const float4*>(pred_scores + (size_t)b * PP);
    for (int i = tid; i < PP / 4; i += 256)
        reinterpret_cast<float4*>(ssc)[i] = sp[i];
    __syncthreads();

    // Merge the 4 quarter results: u64 max == (iou desc, tie -> lower g).
    unsigned long long v = g_pack[(size_t)b * PP + p];
#pragma unroll
    for (int z = 1; z < NZ; ++z) {
        unsigned long long w = g_pack[(size_t)z * BB * PP + (size_t)b * PP + p];
        if (w > v) v = w;
    }
    const int   ginv = (int)(v & 0x1FF);        // 511 - g
    const int   g    = 511 - ginv;
    const float biou = __uint_as_float((unsigned int)(v >> 32));
    const bool  cand = (biou > 0.5f) &&
                       (pred_classes[(size_t)b * PP + p] == gt_classes[(size_t)b * GG + g]);

    const float ms   = ssc[p];
    const int   lane = tid & 31;
    const unsigned full = 0xFFFFFFFFu;

    unsigned int res = 0xFFFFFFFFu;
    unsigned bal = __ballot_sync(full, cand);
    while (bal) {
        int src = __ffs(bal) - 1;
        bal &= bal - 1;
        int   pc = __shfl_sync(full, p,  src);
        float sc = __shfl_sync(full, ms, src);
        int cnt = 0;
        // rank = #(q: score_q > score_p  ||  (score_q == score_p && q < p))
        for (int q = lane; q < PP; q += 32) {
            float sq = ssc[q];
            cnt += (sq > sc) || (sq == sc && q < pc);
        }
        cnt = __reduce_add_sync(full, cnt);
        if (lane == src) res = ((unsigned int)cnt << 9) | (unsigned int)ginv;
    }

    g_cand[(size_t)b * PP + p] = cand ? res : 0xFFFFFFFFu;
}

// ---------------------------------------------------------------------------
// K2b: per image — compact candidates, greedy TP (min rank per gt), AP.
// grid = BB, 256 threads. Deterministic (p-ordered compaction, tree reduce).
// ---------------------------------------------------------------------------
__global__ __launch_bounds__(256) void k_ap2()
{
    const int b   = blockIdx.x;
    const int tid = threadIdx.x;
    const int lane = tid & 31, wid = tid >> 5;

    __shared__ unsigned int  scomp[PP];
    __shared__ unsigned char stp[PP];
    __shared__ int   wsum[8];
    __shared__ float wred[8];

    // Load 8 entries each, count valid, block-scan for p-ordered compaction.
    unsigned int vals[8];
    int c = 0;
    const int base = tid * 8;
#pragma unroll
    for (int k = 0; k < 8; ++k) {
        vals[k] = g_cand[(size_t)b * PP + base + k];
        c += (vals[k] != 0xFFFFFFFFu) ? 1 : 0;
    }
    int sc = c;
    for (int o = 1; o < 32; o <<= 1) {
        int u = __shfl_up_sync(0xFFFFFFFFu, sc, o);
        if (lane >= o) sc += u;
    }
    if (lane == 31) wsum[wid] = sc;
    __syncthreads();
    if (wid == 0 && lane < 8) {
        int u = wsum[lane];
        for (int o = 1; o < 8; o <<= 1) {
            int w = __shfl_up_sync(0xFFu, u, o);
            if (lane >= o) u += w;
        }
        wsum[lane] = u;
    }
    __syncthreads();
    int off = (sc - c) + (wid > 0 ? wsum[wid - 1] : 0);
    const int n = wsum[7];
#pragma unroll
    for (int k = 0; k < 8; ++k)
        if (vals[k] != 0xFFFFFFFFu) scomp[off++] = vals[k];
    __syncthreads();

    // TP iff no other candidate with same gt and smaller rank.
    // packed = (rank<<9)|ginv: same ginv -> same gt; smaller packed -> smaller rank.
    for (int i = tid; i < n; i += 256) {
        unsigned int v = scomp[i];
        int tp = 1;
        for (int j = 0; j < n; ++j) {
            unsigned int w = scomp[j];
            if (w < v && !((w ^ v) & 0x1FFu)) tp = 0;
        }
        stp[i] = (unsigned char)tp;
    }
    __syncthreads();

    // AP terms. For a tp at global rank r (k = r+1), j = 1 + #(tps with rank < r):
    //   term = 0.5 * ( j/k + (k==1 ? 1 : (j-1)/(k-1)) );  AP = sum(term)/G.
    float acc = 0.0f;
    for (int i = tid; i < n; i += 256) {
        if (!stp[i]) continue;
        unsigned int v = scomp[i];
        unsigned int r = v >> 9;
        int j = 1;
        for (int m = 0; m < n; ++m)
            j += (stp[m] && (scomp[m] >> 9) < r) ? 1 : 0;
        float kk = (float)(r + 1);
        float pj = (float)j;
        float prev = (r == 0) ? 1.0f : (pj - 1.0f) / (kk - 1.0f);
        acc += 0.5f * (pj / kk + prev);
    }

    // Deterministic block reduce.
    for (int o = 16; o > 0; o >>= 1) acc += __shfl_down_sync(0xFFFFFFFFu, acc, o);
    if (lane == 0) wred[wid] = acc;
    __syncthreads();
    if (wid == 0 && lane < 8) {
        float u = wred[lane];
        for (int o = 4; o > 0; o >>= 1) u += __shfl_down_sync(0xFFu, u, o);
        if (lane == 0) g_ap[b] = u / (float)GG;
    }
}

// ---------------------------------------------------------------------------
// K3: deterministic mean of 64 per-image APs.
// ---------------------------------------------------------------------------
__global__ void k_mean(float* __restrict__ out)
{
    int lane = threadIdx.x;   // one warp
    float v = g_ap[lane] + g_ap[lane + 32];
    for (int o = 16; o > 0; o >>= 1) v += __shfl_down_sync(0xFFFFFFFFu, v, o);
    if (lane == 0) out[0] = v * (1.0f / (float)BB);
}

// ---------------------------------------------------------------------------
extern "C" void kernel_launch(void* const* d_in, const int* in_sizes, int n_in,
                              void* d_out, int out_size)
{
    const float* pred_boxes   = (const float*)d_in[0];
    const float* pred_scores  = (const float*)d_in[1];
    const int*   pred_classes = (const int*)d_in[2];
    const float* gt_boxes     = (const float*)d_in[3];
    const int*   gt_classes   = (const int*)d_in[4];
    float* out = (float*)d_out;

    dim3 g1(PP / 512, BB, NZ);
    k_bestiou<<<g1, 256>>>(pred_boxes, gt_boxes);
    dim3 g2(PP / 256, BB);
    k_cand<<<g2, 256>>>(pred_scores, pred_classes, gt_classes);
    k_ap2<<<BB, 256>>>();
    k_mean<<<1, 32>>>(out);
}

// round 7
// speedup vs baseline: 1.2654x; 1.0378x over previous
#include <cuda_runtime.h>
#include <stdint.h>

// Problem shapes (fixed by the dataset).
#define BB 64
#define PP 2048
#define GG 512
#define NZ 8
#define GH (GG / NZ)    // 64 gts per tile

// Scratch. Packed per (tile, image, pred): (iou_bits<<32) | (511 - g_global).
__device__ unsigned long long g_pack[NZ * BB * PP];
// Dense per (image, pred): (rank<<9) | ginv, ginv = 511 - g. 0xFFFFFFFF = no cand.
__device__ unsigned int g_cand[BB * PP];
__device__ float g_ap[BB];
__device__ unsigned int g_ticket;   // zero-init; self-resetting via atomicInc wrap

// ---------------------------------------------------------------------------
// K1: per (image, pred, gt-tile) first-max argmax_g IoU + max value.
// 256 threads, 2 preds/thread, 64 gts in smem. grid = (PP/512, BB, NZ).
// ---------------------------------------------------------------------------
__global__ __launch_bounds__(256) void k_bestiou(
    const float* __restrict__ pred_boxes,   // [B,P,4] xywh
    const float* __restrict__ gt_boxes)     // [B,G,4] xywh
{
    const int b  = blockIdx.y;
    const int zh = blockIdx.z;
    const int p0 = blockIdx.x * 512 + threadIdx.x;
    const int p1 = p0 + 256;

    __shared__ float4 sbox[GH];   // x1,y1,x2,y2
    __shared__ float  sarea[GH];

    const float4* gbp = reinterpret_cast<const float4*>(
        gt_boxes + ((size_t)b * GG + (size_t)zh * GH) * 4);
    if (threadIdx.x < GH) {
        float4 v = gbp[threadIdx.x];
        float x2 = v.x + v.z;
        float y2 = v.y + v.w;
        sbox[threadIdx.x]  = make_float4(v.x, v.y, x2, y2);
        sarea[threadIdx.x] = fabsf((x2 - v.x) * (y2 - v.y));
    }
    __syncthreads();

    const float4* pbp = reinterpret_cast<const float4*>(pred_boxes + (size_t)b * PP * 4);
    float4 a = pbp[p0];
    float4 c = pbp[p1];
    const float ax1 = a.x, ay1 = a.y, ax2 = a.x + a.z, ay2 = a.y + a.w;
    const float cx1 = c.x, cy1 = c.y, cx2 = c.x + c.z, cy2 = c.y + c.w;
    const float aa = fabsf((ax2 - ax1) * (ay2 - ay1)) + 1e-9f;  // pa + eps hoisted
    const float ca = fabsf((cx2 - cx1) * (cy2 - cy1)) + 1e-9f;

    float best0 = -1.0f, best1 = -1.0f;
    int   bg0 = 0, bg1 = 0;

#pragma unroll 4
    for (int g = 0; g < GH; ++g) {
        float4 gb = sbox[g];
        float sa  = sarea[g];
        {
            float ix1 = fmaxf(ax1, gb.x);
            float iy1 = fmaxf(ay1, gb.y);
            float ix2 = fminf(ax2, gb.z);
            float iy2 = fminf(ay2, gb.w);
            float iw  = ix2 - ix1;                 // clamp dropped: inter<=0 if iw<0
            float ih  = fmaxf(iy2 - iy1, 0.0f);
            float inter = iw * ih;
            float u   = (aa + sa) - inter;
            float iou = __fdividef(inter, u);
            if (iou > best0) { best0 = iou; bg0 = g; }   // strict > keeps FIRST max
        }
        {
            float ix1 = fmaxf(cx1, gb.x);
            float iy1 = fmaxf(cy1, gb.y);
            float ix2 = fminf(cx2, gb.z);
            float iy2 = fminf(cy2, gb.w);
            float iw  = ix2 - ix1;
            float ih  = fmaxf(iy2 - iy1, 0.0f);
            float inter = iw * ih;
            float u   = (ca + sa) - inter;
            float iou = __fdividef(inter, u);
            if (iou > best1) { best1 = iou; bg1 = g; }
        }
    }

    // Clamp negatives to 0 so the u64 merge (unsigned compare) stays monotonic.
    // A clamped-to-0 best can only "win" when the global max <= 0.5 (harmless).
    best0 = fmaxf(best0, 0.0f);
    best1 = fmaxf(best1, 0.0f);

    const int goff = zh * GH;
    unsigned long long* outp = g_pack + (size_t)zh * BB * PP + (size_t)b * PP;
    outp[p0] = ((unsigned long long)__float_as_uint(best0) << 32)
             | (unsigned int)(511 - (bg0 + goff));
    outp[p1] = ((unsigned long long)__float_as_uint(best1) << 32)
             | (unsigned int)(511 - (bg1 + goff));
}

// ---------------------------------------------------------------------------
// K2a: merge tiles, detect candidates, compute exact stable-sort rank for
// candidates only (warp-cooperative count). Writes dense g_cand.
// grid = (PP/256, BB), 256 threads.
// ---------------------------------------------------------------------------
__global__ __launch_bounds__(256) void k_cand(
    const float* __restrict__ pred_scores,   // [B,P]
    const int*   __restrict__ pred_classes,  // [B,P]
    const int*   __restrict__ gt_classes)    // [B,G]
{
    const int b   = blockIdx.y;
    const int tid = threadIdx.x;
    const int p   = blockIdx.x * 256 + tid;

    __shared__ float ssc[PP];   // all scores of image b

    const float4* sp = reinterpret_cast<const float4*>(pred_scores + (size_t)b * PP);
    for (int i = tid; i < PP / 4; i += 256)
        reinterpret_cast<float4*>(ssc)[i] = sp[i];
    __syncthreads();

    // Merge NZ tile results: u64 max == (iou desc, tie -> lower g).
    unsigned long long v = g_pack[(size_t)b * PP + p];
#pragma unroll
    for (int z = 1; z < NZ; ++z) {
        unsigned long long w = g_pack[(size_t)z * BB * PP + (size_t)b * PP + p];
        if (w > v) v = w;
    }
    const int   ginv = (int)(v & 0x1FF);        // 511 - g
    const int   g    = 511 - ginv;
    const float biou = __uint_as_float((unsigned int)(v >> 32));
    const bool  cand = (biou > 0.5f) &&
                       (pred_classes[(size_t)b * PP + p] == gt_classes[(size_t)b * GG + g]);

    const float ms   = ssc[p];
    const int   lane = tid & 31;
    const unsigned full = 0xFFFFFFFFu;

    unsigned int res = 0xFFFFFFFFu;
    unsigned bal = __ballot_sync(full, cand);
    while (bal) {
        int src = __ffs(bal) - 1;
        bal &= bal - 1;
        int   pc = __shfl_sync(full, p,  src);
        float sc = __shfl_sync(full, ms, src);
        int cnt = 0;
        // rank = #(q: score_q > score_p  ||  (score_q == score_p && q < p))
        for (int q = lane; q < PP; q += 32) {
            float sq = ssc[q];
            cnt += (sq > sc) || (sq == sc && q < pc);
        }
        cnt = __reduce_add_sync(full, cnt);
        if (lane == src) res = ((unsigned int)cnt << 9) | (unsigned int)ginv;
    }

    g_cand[(size_t)b * PP + p] = cand ? res : 0xFFFFFFFFu;
}

// ---------------------------------------------------------------------------
// K2b: per image — compact candidates, greedy TP (min rank per gt), AP.
// Last block (ticket) computes the batch mean. grid = BB, 256 threads.
// ---------------------------------------------------------------------------
__global__ __launch_bounds__(256) void k_ap2(float* __restrict__ out)
{
    const int b   = blockIdx.x;
    const int tid = threadIdx.x;
    const int lane = tid & 31, wid = tid >> 5;

    __shared__ unsigned int  scomp[PP];
    __shared__ unsigned char stp[PP];
    __shared__ int   wsum[8];
    __shared__ float wred[8];

    // Load 8 entries each, count valid, block-scan for p-ordered compaction.
    unsigned int vals[8];
    int c = 0;
    const int base = tid * 8;
#pragma unroll
    for (int k = 0; k < 8; ++k) {
        vals[k] = g_cand[(size_t)b * PP + base + k];
        c += (vals[k] != 0xFFFFFFFFu) ? 1 : 0;
    }
    int sc = c;
    for (int o = 1; o < 32; o <<= 1) {
        int u = __shfl_up_sync(0xFFFFFFFFu, sc, o);
        if (lane >= o) sc += u;
    }
    if (lane == 31) wsum[wid] = sc;
    __syncthreads();
    if (wid == 0 && lane < 8) {
        int u = wsum[lane];
        for (int o = 1; o < 8; o <<= 1) {
            int w = __shfl_up_sync(0xFFu, u, o);
            if (lane >= o) u += w;
        }
        wsum[lane] = u;
    }
    __syncthreads();
    int off = (sc - c) + (wid > 0 ? wsum[wid - 1] : 0);
    const int n = wsum[7];
#pragma unroll
    for (int k = 0; k < 8; ++k)
        if (vals[k] != 0xFFFFFFFFu) scomp[off++] = vals[k];
    __syncthreads();

    // TP iff no other candidate with same gt and smaller rank.
    // packed = (rank<<9)|ginv: same ginv -> same gt; smaller packed -> smaller rank.
    for (int i = tid; i < n; i += 256) {
        unsigned int v = scomp[i];
        int tp = 1;
        for (int j = 0; j < n; ++j) {
            unsigned int w = scomp[j];
            if (w < v && !((w ^ v) & 0x1FFu)) tp = 0;
        }
        stp[i] = (unsigned char)tp;
    }
    __syncthreads();

    // AP terms. For a tp at global rank r (k = r+1), j = 1 + #(tps with rank < r):
    //   term = 0.5 * ( j/k + (k==1 ? 1 : (j-1)/(k-1)) );  AP = sum(term)/G.
    float acc = 0.0f;
    for (int i = tid; i < n; i += 256) {
        if (!stp[i]) continue;
        unsigned int v = scomp[i];
        unsigned int r = v >> 9;
        int j = 1;
        for (int m = 0; m < n; ++m)
            j += (stp[m] && (scomp[m] >> 9) < r) ? 1 : 0;
        float kk = (float)(r + 1);
        float pj = (float)j;
        float prev = (r == 0) ? 1.0f : (pj - 1.0f) / (kk - 1.0f);
        acc += 0.5f * (pj / kk + prev);
    }

    // Deterministic block reduce.
    for (int o = 16; o > 0; o >>= 1) acc += __shfl_down_sync(0xFFFFFFFFu, acc, o);
    if (lane == 0) wred[wid] = acc;
    __syncthreads();
    if (tid == 0) {
        float u = 0.0f;
#pragma unroll
        for (int w = 0; w < 8; ++w) u += wred[w];
        g_ap[b] = u / (float)GG;

        // Ticket: last block computes the mean. atomicInc wraps 63 -> 0, so the
        // counter self-resets for every graph replay (deterministic work/output).
        __threadfence();
        unsigned old = atomicInc(&g_ticket, BB - 1);
        if (old == BB - 1) {
            float s = 0.0f;
#pragma unroll
            for (int i = 0; i < BB; ++i) s += g_ap[i];   // fixed order
            out[0] = s * (1.0f / (float)BB);
        }
    }
}

// ---------------------------------------------------------------------------
extern "C" void kernel_launch(void* const* d_in, const int* in_sizes, int n_in,
                              void* d_out, int out_size)
{
    const float* pred_boxes   = (const float*)d_in[0];
    const float* pred_scores  = (const float*)d_in[1];
    const int*   pred_classes = (const int*)d_in[2];
    const float* gt_boxes     = (const float*)d_in[3];
    const int*   gt_classes   = (const int*)d_in[4];
    float* out = (float*)d_out;

    dim3 g1(PP / 512, BB, NZ);
    k_bestiou<<<g1, 256>>>(pred_boxes, gt_boxes);
    dim3 g2(PP / 256, BB);
    k_cand<<<g2, 256>>>(pred_scores, pred_classes, gt_classes);
    k_ap2<<<BB, 256>>>(out);
}

// round 8
// speedup vs baseline: 1.2673x; 1.0015x over previous
#include <cuda_runtime.h>
#include <stdint.h>

// Problem shapes (fixed by the dataset).
#define BB 64
#define PP 2048
#define GG 512
#define NZ 16
#define GH (GG / NZ)    // 32 gts per tile

// Merged best per (image, pred): (iou_bits<<32) | (511 - g). Zero-initialized;
// K2a resets each element to 0 after consuming it (replay-safe).
__device__ unsigned long long g_best[BB * PP];
// Dense per (image, pred): (rank<<9) | ginv, ginv = 511 - g. 0xFFFFFFFF = no cand.
__device__ unsigned int g_cand[BB * PP];
__device__ float g_ap[BB];
__device__ unsigned int g_ticket;   // zero-init; self-resetting via atomicInc wrap

// ---------------------------------------------------------------------------
// K1: per (image, pred, gt-tile) first-max argmax_g IoU + max value, merged
// globally via atomicMax(u64). 256 threads, 4 preds/thread, 32 gts in smem.
// grid = (PP/1024, BB, NZ).
// ---------------------------------------------------------------------------
__global__ __launch_bounds__(256, 5) void k_bestiou(
    const float* __restrict__ pred_boxes,   // [B,P,4] xywh
    const float* __restrict__ gt_boxes)     // [B,G,4] xywh
{
    const int b  = blockIdx.y;
    const int zt = blockIdx.z;
    const int pb = blockIdx.x * 1024 + threadIdx.x;   // preds pb + {0,256,512,768}

    __shared__ float4 sbox[GH];   // x1,y1,x2,y2
    __shared__ float  sarea[GH];

    const float4* gbp = reinterpret_cast<const float4*>(
        gt_boxes + ((size_t)b * GG + (size_t)zt * GH) * 4);
    if (threadIdx.x < GH) {
        float4 v = gbp[threadIdx.x];
        float x2 = v.x + v.z;
        float y2 = v.y + v.w;
        sbox[threadIdx.x]  = make_float4(v.x, v.y, x2, y2);
        sarea[threadIdx.x] = fabsf((x2 - v.x) * (y2 - v.y));
    }
    __syncthreads();

    const float4* pbp = reinterpret_cast<const float4*>(pred_boxes + (size_t)b * PP * 4);
    float px1[4], py1[4], px2[4], py2[4], pae[4];
#pragma unroll
    for (int k = 0; k < 4; ++k) {
        float4 v = pbp[pb + k * 256];
        px1[k] = v.x;
        py1[k] = v.y;
        px2[k] = v.x + v.z;
        py2[k] = v.y + v.w;
        pae[k] = fabsf((px2[k] - px1[k]) * (py2[k] - py1[k])) + 1e-9f;  // area + eps
    }

    // Init 0: negatives/zeros never update (matches reference; all-<=0 rows
    // resolve to g = tile start, and the global merge then picks g = 0).
    float best[4] = {0.0f, 0.0f, 0.0f, 0.0f};
    int   bg[4]   = {0, 0, 0, 0};

#pragma unroll 8
    for (int g = 0; g < GH; ++g) {
        float4 gb = sbox[g];
        float sa  = sarea[g];
#pragma unroll
        for (int k = 0; k < 4; ++k) {
            float ix1 = fmaxf(px1[k], gb.x);
            float iy1 = fmaxf(py1[k], gb.y);
            float ix2 = fminf(px2[k], gb.z);
            float iy2 = fminf(py2[k], gb.w);
            float iw  = ix2 - ix1;                 // unclamped: inter<=0 if no x-overlap
            float ih  = fmaxf(iy2 - iy1, 0.0f);    // one clamp avoids neg*neg
            float inter = iw * ih;
            float u   = (pae[k] + sa) - inter;     // union + eps, always > 0
            float iou = __fdividef(inter, u);
            if (iou > best[k]) { best[k] = iou; bg[k] = g; }  // strict > = first max
        }
    }

    const int goff = zt * GH;
#pragma unroll
    for (int k = 0; k < 4; ++k) {
        unsigned long long pack =
            ((unsigned long long)__float_as_uint(best[k]) << 32)
            | (unsigned int)(511 - (bg[k] + goff));
        atomicMax(&g_best[(size_t)b * PP + pb + k * 256], pack);
    }
}

// ---------------------------------------------------------------------------
// K2a: consume merged best (and reset it for the next graph replay), detect
// candidates, compute exact stable-sort rank for candidates only
// (warp-cooperative count). grid = (PP/256, BB), 256 threads.
// ---------------------------------------------------------------------------
__global__ __launch_bounds__(256) void k_cand(
    const float* __restrict__ pred_scores,   // [B,P]
    const int*   __restrict__ pred_classes,  // [B,P]
    const int*   __restrict__ gt_classes)    // [B,G]
{
    const int b   = blockIdx.y;
    const int tid = threadIdx.x;
    const int p   = blockIdx.x * 256 + tid;

    __shared__ float ssc[PP];   // all scores of image b

    const float4* sp = reinterpret_cast<const float4*>(pred_scores + (size_t)b * PP);
    for (int i = tid; i < PP / 4; i += 256)
        reinterpret_cast<float4*>(ssc)[i] = sp[i];
    __syncthreads();

    const size_t idx = (size_t)b * PP + p;
    unsigned long long v = g_best[idx];
    g_best[idx] = 0ULL;   // reset for next replay (this thread is sole reader)

    const int   ginv = (int)(v & 0x1FF);        // 511 - g
    const int   g    = 511 - ginv;
    const float biou = __uint_as_float((unsigned int)(v >> 32));
    const bool  cand = (biou > 0.5f) &&
                       (pred_classes[idx] == gt_classes[(size_t)b * GG + g]);

    const float ms   = ssc[p];
    const int   lane = tid & 31;
    const unsigned full = 0xFFFFFFFFu;

    unsigned int res = 0xFFFFFFFFu;
    unsigned bal = __ballot_sync(full, cand);
    while (bal) {
        int src = __ffs(bal) - 1;
        bal &= bal - 1;
        int   pc = __shfl_sync(full, p,  src);
        float sc = __shfl_sync(full, ms, src);
        int cnt = 0;
        // rank = #(q: score_q > score_p  ||  (score_q == score_p && q < p))
        for (int q = lane; q < PP; q += 32) {
            float sq = ssc[q];
            cnt += (sq > sc) || (sq == sc && q < pc);
        }
        cnt = __reduce_add_sync(full, cnt);
        if (lane == src) res = ((unsigned int)cnt << 9) | (unsigned int)ginv;
    }

    g_cand[idx] = cand ? res : 0xFFFFFFFFu;
}

// ---------------------------------------------------------------------------
// K2b: per image — compact candidates, greedy TP (min rank per gt), AP.
// Last block (ticket) computes the batch mean. grid = BB, 256 threads.
// ---------------------------------------------------------------------------
__global__ __launch_bounds__(256) void k_ap2(float* __restrict__ out)
{
    const int b   = blockIdx.x;
    const int tid = threadIdx.x;
    const int lane = tid & 31, wid = tid >> 5;

    __shared__ unsigned int  scomp[PP];
    __shared__ unsigned char stp[PP];
    __shared__ int   wsum[8];
    __shared__ float wred[8];

    // Load 8 entries each, count valid, block-scan for p-ordered compaction.
    unsigned int vals[8];
    int c = 0;
    const int base = tid * 8;
#pragma unroll
    for (int k = 0; k < 8; ++k) {
        vals[k] = g_cand[(size_t)b * PP + base + k];
        c += (vals[k] != 0xFFFFFFFFu) ? 1 : 0;
    }
    int sc = c;
    for (int o = 1; o < 32; o <<= 1) {
        int u = __shfl_up_sync(0xFFFFFFFFu, sc, o);
        if (lane >= o) sc += u;
    }
    if (lane == 31) wsum[wid] = sc;
    __syncthreads();
    if (wid == 0 && lane < 8) {
        int u = wsum[lane];
        for (int o = 1; o < 8; o <<= 1) {
            int w = __shfl_up_sync(0xFFu, u, o);
            if (lane >= o) u += w;
        }
        wsum[lane] = u;
    }
    __syncthreads();
    int off = (sc - c) + (wid > 0 ? wsum[wid - 1] : 0);
    const int n = wsum[7];
#pragma unroll
    for (int k = 0; k < 8; ++k)
        if (vals[k] != 0xFFFFFFFFu) scomp[off++] = vals[k];
    __syncthreads();

    // TP iff no other candidate with same gt and smaller rank.
    // packed = (rank<<9)|ginv: same ginv -> same gt; smaller packed -> smaller rank.
    for (int i = tid; i < n; i += 256) {
        unsigned int v = scomp[i];
        int tp = 1;
        for (int j = 0; j < n; ++j) {
            unsigned int w = scomp[j];
            if (w < v && !((w ^ v) & 0x1FFu)) tp = 0;
        }
        stp[i] = (unsigned char)tp;
    }
    __syncthreads();

    // AP terms. For a tp at global rank r (k = r+1), j = 1 + #(tps with rank < r):
    //   term = 0.5 * ( j/k + (k==1 ? 1 : (j-1)/(k-1)) );  AP = sum(term)/G.
    float acc = 0.0f;
    for (int i = tid; i < n; i += 256) {
        if (!stp[i]) continue;
        unsigned int v = scomp[i];
        unsigned int r = v >> 9;
        int j = 1;
        for (int m = 0; m < n; ++m)
            j += (stp[m] && (scomp[m] >> 9) < r) ? 1 : 0;
        float kk = (float)(r + 1);
        float pj = (float)j;
        float prev = (r == 0) ? 1.0f : (pj - 1.0f) / (kk - 1.0f);
        acc += 0.5f * (pj / kk + prev);
    }

    // Deterministic block reduce.
    for (int o = 16; o > 0; o >>= 1) acc += __shfl_down_sync(0xFFFFFFFFu, acc, o);
    if (lane == 0) wred[wid] = acc;
    __syncthreads();
    if (tid == 0) {
        float u = 0.0f;
#pragma unroll
        for (int w = 0; w < 8; ++w) u += wred[w];
        g_ap[b] = u / (float)GG;

        // Ticket: last block computes the mean. atomicInc wraps 63 -> 0, so the
        // counter self-resets for every graph replay (deterministic work/output).
        __threadfence();
        unsigned old = atomicInc(&g_ticket, BB - 1);
        if (old == BB - 1) {
            float s = 0.0f;
#pragma unroll
            for (int i = 0; i < BB; ++i) s += g_ap[i];   // fixed order
            out[0] = s * (1.0f / (float)BB);
        }
    }
}

// ---------------------------------------------------------------------------
extern "C" void kernel_launch(void* const* d_in, const int* in_sizes, int n_in,
                              void* d_out, int out_size)
{
    const float* pred_boxes   = (const float*)d_in[0];
    const float* pred_scores  = (const float*)d_in[1];
    const int*   pred_classes = (const int*)d_in[2];
    const float* gt_boxes     = (const float*)d_in[3];
    const int*   gt_classes   = (const int*)d_in[4];
    float* out = (float*)d_out;

    dim3 g1(PP / 1024, BB, NZ);
    k_bestiou<<<g1, 256>>>(pred_boxes, gt_boxes);
    dim3 g2(PP / 256, BB);
    k_cand<<<g2, 256>>>(pred_scores, pred_classes, gt_classes);
    k_ap2<<<BB, 256>>>(out);
}